// round 7
// baseline (speedup 1.0000x reference)
#include <cuda_runtime.h>
#include <stdint.h>

// ============================================================================
// JMEFairnessLoss — SINGLE kernel:
//   phase A: truth row-sum + threshold top-100 (exact radix fallback)
//   phase B: gumbel soft-rank exposure via ANTISYMMETRIC circulant tanh
//            (4950 tanh/sample instead of 10000)
//   epilogue: fixed-point integer atomics (deterministic) + last-block
//             ticket finalize -> (total, ii, gg); accumulators self-reset.
// ============================================================================

namespace jme {
constexpr int B      = 1024;
constexpr int NITEMS = 10000;
constexpr int TOPK   = 100;
constexpr int NS     = 10;
constexpr int NIG    = 16;
constexpr int NPAIR  = 128;
constexpr int NTASK  = NS * TOPK;     // 1000
constexpr int CAND   = 256;
}

// ---- global accumulators (all raw sums are >= 0; fixed-point, exact) ------
__device__ unsigned long long g_pairD[jme::NPAIR];   // sum e  * 2^32 per (ug,ig)
__device__ unsigned int       g_pairC[jme::NPAIR];   // counts (exact ints)
__device__ unsigned long long g_sq;                  // sum e^2 * 2^32
__device__ unsigned long long g_sl;                  // sum e   * 2^32
__device__ unsigned long long g_ts;                  // sum truth * 2^26
__device__ unsigned int       g_done;

// ------------------------------- threefry2x32 (JAX-exact, key=(0,1)) -------
__device__ __forceinline__ void tf_round(uint32_t& x0, uint32_t& x1, int r) {
    x0 += x1;
    x1 = __funnelshift_l(x1, x1, r);
    x1 ^= x0;
}
__device__ __forceinline__ uint2 threefry01(uint32_t x0, uint32_t x1) {
    const uint32_t k0 = 0u, k1 = 1u, k2 = 0x1BD11BDBu;
    x0 += k0; x1 += k1;
    tf_round(x0,x1,13); tf_round(x0,x1,15); tf_round(x0,x1,26); tf_round(x0,x1,6);
    x0 += k1; x1 += k2 + 1u;
    tf_round(x0,x1,17); tf_round(x0,x1,29); tf_round(x0,x1,16); tf_round(x0,x1,24);
    x0 += k2; x1 += k0 + 2u;
    tf_round(x0,x1,13); tf_round(x0,x1,15); tf_round(x0,x1,26); tf_round(x0,x1,6);
    x0 += k0; x1 += k1 + 3u;
    tf_round(x0,x1,17); tf_round(x0,x1,29); tf_round(x0,x1,16); tf_round(x0,x1,24);
    x0 += k1; x1 += k2 + 4u;
    tf_round(x0,x1,13); tf_round(x0,x1,15); tf_round(x0,x1,26); tf_round(x0,x1,6);
    x0 += k2; x1 += k0 + 5u;
    return make_uint2(x0, x1);
}
__device__ __forceinline__ float gumbel_at(int lin) {
    uint2 r = threefry01(0u, (uint32_t)lin);
    uint32_t bits = r.x ^ r.y;
    float f = __uint_as_float((bits >> 9) | 0x3F800000u) - 1.0f;
    float u = fmaxf(1.17549435e-38f, f);
    return -__logf(-__logf(u));
}

// ------------------------------- key helpers -------------------------------
__device__ __forceinline__ uint32_t f2key(float f) {
    uint32_t u = __float_as_uint(f);
    return (u & 0x80000000u) ? ~u : (u | 0x80000000u);
}
__device__ __forceinline__ float key2f(uint32_t k) {
    uint32_t fb = (k & 0x80000000u) ? (k ^ 0x80000000u) : ~k;
    return __uint_as_float(fb);
}

// ------------------------------- the kernel --------------------------------
__global__ __launch_bounds__(256) void k_row(const float* __restrict__ pred,
                                             const float* __restrict__ truth,
                                             const int*   __restrict__ item_groups,
                                             const int*   __restrict__ user_groups,
                                             float* __restrict__ out) {
    // Sbuf aliases: cand(ull[256]) @0 | red/hist @float 1024 | stage/expo full
    __shared__ __align__(16) float Sbuf[7000];       // 28 KB
    __shared__ float nz[jme::NS][jme::TOPK];         // noisy * 5
    __shared__ float sval[jme::TOPK];
    __shared__ int   s_ig[jme::TOPK];
    __shared__ float sdelta[jme::TOPK];
    __shared__ int s_cnt;
    __shared__ uint32_t s_prefix;
    __shared__ int s_rem;
    __shared__ int s_ticket;

    unsigned long long* cand = (unsigned long long*)Sbuf;   // [0..255] -> 2KB
    float*    red  = Sbuf + 1024;                           // truth reduce
    uint32_t* hist = (uint32_t*)(Sbuf + 1024);              // fallback only

    const int row = blockIdx.x, tid = threadIdx.x;
    const float4* rp4 = (const float4*)(pred  + (size_t)row * jme::NITEMS);
    const float4* tr4 = (const float4*)(truth + (size_t)row * jme::NITEMS);
    constexpr int N4 = jme::NITEMS / 4;              // 2500

    // =============== phase A: truth sum + top-100 gather ===================
    cand[tid] = 0ULL;
    if (tid == 0) s_cnt = 0;
    __syncthreads();

    const float THR = 2.10f;   // N(0,1): E[count>THR]=178, sd=13 (cap 256)
    float tsum = 0.0f;
    #pragma unroll 5
    for (int c = tid; c < N4; c += 256) {
        float4 v  = rp4[c];
        float4 tv = tr4[c];
        tsum += (tv.x + tv.y) + (tv.z + tv.w);
        const float vv[4] = {v.x, v.y, v.z, v.w};
        #pragma unroll
        for (int e = 0; e < 4; ++e) {
            if (vv[e] > THR) {
                int pos = atomicAdd(&s_cnt, 1);
                if (pos < jme::CAND)
                    cand[pos] = (((unsigned long long)f2key(vv[e])) << 32)
                              | (uint32_t)(0xFFFFFFFFu - (uint32_t)(4 * c + e));
            }
        }
    }
    red[tid] = tsum;
    __syncthreads();
    for (int o = 128; o > 0; o >>= 1) {
        if (tid < o) red[tid] += red[tid + o];
        __syncthreads();
    }
    if (tid == 0)
        atomicAdd(&g_ts, (unsigned long long)__double2ll_rn((double)red[0] * 67108864.0));
    __syncthreads();

    // exact fallback (statistically never taken; correctness for any input)
    if (s_cnt < jme::TOPK || s_cnt > jme::CAND) {
        const float* rp = pred + (size_t)row * jme::NITEMS;
        if (tid == 0) { s_rem = jme::TOPK; s_prefix = 0u; }
        __syncthreads();
        uint32_t prefix = 0u;
        for (int shift = 24; shift >= 0; shift -= 8) {
            hist[tid] = 0u;
            __syncthreads();
            const uint32_t himask = (shift == 24) ? 0u : (0xFFFFFFFFu << (shift + 8));
            for (int i = tid; i < jme::NITEMS; i += 256) {
                uint32_t k = f2key(rp[i]);
                if ((k & himask) == prefix)
                    atomicAdd(&hist[(k >> shift) & 0xFF], 1u);
            }
            __syncthreads();
            if (tid == 0) {
                int cum = 0, sel = 0;
                for (int b = 255; b >= 0; --b) {
                    int h = (int)hist[b];
                    if (cum + h >= s_rem) { sel = b; s_rem -= cum; break; }
                    cum += h;
                }
                s_prefix = prefix | ((uint32_t)sel << shift);
            }
            __syncthreads();
            prefix = s_prefix;
            __syncthreads();
        }
        const uint32_t T = prefix;   // exact 100th-largest key
        cand[tid] = 0ULL;
        if (tid == 0) s_cnt = 0;
        __syncthreads();
        for (int i = tid; i < jme::NITEMS; i += 256) {
            uint32_t k = f2key(rp[i]);
            if (k >= T) {
                int pos = atomicAdd(&s_cnt, 1);
                if (pos < jme::CAND)
                    cand[pos] = (((unsigned long long)k) << 32)
                              | (uint32_t)(0xFFFFFFFFu - (uint32_t)i);
            }
        }
        __syncthreads();
    }

    // rank-by-count: rank = #{j : cand[j] > cand[i]}; scatter top-100
    {
        unsigned long long e = cand[tid];
        int r = 0;
        #pragma unroll 8
        for (int j = 0; j < jme::CAND; ++j) r += (cand[j] > e);
        if (e != 0ULL && r < jme::TOPK) {
            sval[r] = key2f((uint32_t)(e >> 32));
            s_ig[r] = item_groups[0xFFFFFFFFu - (uint32_t)e];
        }
    }
    __syncthreads();

    // =============== phase B: exposure via antisymmetric circulant =========
    for (int tk = tid; tk < jme::NTASK; tk += 256) {
        int s = tk / jme::TOPK, i = tk - s * jme::TOPK;
        int lin = (s * jme::B + row) * jme::TOPK + i;
        nz[s][i] = (sval[i] + gumbel_at(lin)) * 5.0f;
    }
    __syncthreads();

    // ownership: thread owns tasks tk = tid + 256*m
    float racc[4] = {0.f, 0.f, 0.f, 0.f};
    float vi[4];
    int sI[4], iI[4];
    const int own = (tid < 232) ? 4 : 3;   // 232*4 + 24*3 = 1000
    #pragma unroll
    for (int m = 0; m < 4; ++m) {
        int tk = tid + 256 * m;
        int s = (tk < jme::NTASK) ? (tk / 100) : 0;
        int i = (tk < jme::NTASK) ? (tk - 100 * s) : 0;
        sI[m] = s; iI[m] = i;
        vi[m] = nz[s][i];
    }

    // d = 1..49 in 7 staged groups of 7
    for (int d0 = 1; d0 <= 43; d0 += 7) {
        for (int m = 0; m < own; ++m) {
            const float* rowv = nz[sI[m]];
            const int base = sI[m] * 100 + iI[m];
            #pragma unroll
            for (int g = 0; g < 7; ++g) {
                int jp = iI[m] + d0 + g; if (jp >= 100) jp -= 100;
                float t;
                asm("tanh.approx.f32 %0, %1;" : "=f"(t) : "f"(vi[m] - rowv[jp]));
                racc[m] += t;
                Sbuf[g * 1000 + base] = t;
            }
        }
        __syncthreads();
        for (int m = 0; m < own; ++m) {
            const int base = sI[m] * 100;
            #pragma unroll
            for (int g = 0; g < 7; ++g) {
                int jm = iI[m] - (d0 + g); if (jm < 0) jm += 100;
                racc[m] -= Sbuf[g * 1000 + base + jm];
            }
        }
        __syncthreads();
    }
    // d = 50 (half-range)
    for (int m = 0; m < own; ++m) {
        if (iI[m] < 50) {
            float t;
            asm("tanh.approx.f32 %0, %1;" : "=f"(t) : "f"(vi[m] - nz[sI[m]][iI[m] + 50]));
            racc[m] += t;
            Sbuf[sI[m] * 100 + iI[m]] = t;
        }
    }
    __syncthreads();
    for (int m = 0; m < own; ++m)
        if (iI[m] >= 50) racc[m] -= Sbuf[sI[m] * 100 + iI[m] - 50];
    __syncthreads();

    // exposure per task -> Sbuf[s*100+i]
    const float L2G = -0.3219280948873623f;     // log2(0.8)
    for (int m = 0; m < own; ++m) {
        float ex;
        asm("ex2.approx.f32 %0, %1;" : "=f"(ex)
            : "f"(fmaf(racc[m], 0.5f * L2G, 49.5f * L2G)));
        Sbuf[sI[m] * 100 + iI[m]] = ex;
    }
    __syncthreads();

    if (tid < jme::TOPK) {
        float acc = 0.0f;
        #pragma unroll
        for (int s = 0; s < jme::NS; ++s) acc += Sbuf[s * 100 + tid];
        sdelta[tid] = acc * 0.1f;           // raw e_i (t deferred)
    }
    __syncthreads();

    // =============== per-row partials -> global integer atomics ============
    if (tid == 0) {
        float sq = 0.0f, sl = 0.0f;
        for (int i = 0; i < jme::TOPK; ++i) {
            float e = sdelta[i];
            sq += e * e; sl += e;
        }
        atomicAdd(&g_sq, (unsigned long long)__double2ll_rn((double)sq * 4294967296.0));
        atomicAdd(&g_sl, (unsigned long long)__double2ll_rn((double)sl * 4294967296.0));
    }
    if (tid < jme::NIG) {
        float sD = 0.0f, c = 0.0f;
        for (int i = 0; i < jme::TOPK; ++i)
            if (s_ig[i] == tid) { sD += sdelta[i]; c += 1.0f; }
        const int ug = user_groups[row];
        atomicAdd(&g_pairD[ug * jme::NIG + tid],
                  (unsigned long long)__double2ll_rn((double)sD * 4294967296.0));
        atomicAdd(&g_pairC[ug * jme::NIG + tid], (unsigned int)c);
    }

    // =============== last-block ticket: finalize ============================
    __threadfence();
    if (tid == 0) s_ticket = (int)atomicAdd(&g_done, 1u);
    __syncthreads();
    if (s_ticket == jme::B - 1) {
        const double t = (double)(long long)__ldcg((const long long*)&g_ts)
                         / 67108864.0 / (double)(jme::B * jme::NITEMS);
        float a2 = 0.0f;
        if (tid < jme::NPAIR) {
            double D = (double)(long long)__ldcg((const long long*)&g_pairD[tid])
                       / 4294967296.0;
            double C = (double)__ldcg((const unsigned int*)&g_pairC[tid]);
            double avg = (C > 0.0) ? ((D - t * C) / fmax(C, 1.0)) : 0.0;
            a2 = (float)(avg * avg);
        }
        red[tid] = a2;
        __syncthreads();
        for (int o = 128; o > 0; o >>= 1) {
            if (tid < o) red[tid] += red[tid + o];
            __syncthreads();
        }
        if (tid == 0) {
            const double BK = (double)(jme::B * jme::TOPK);
            double Sq = (double)(long long)__ldcg((const long long*)&g_sq) / 4294967296.0;
            double Sl = (double)(long long)__ldcg((const long long*)&g_sl) / 4294967296.0;
            const float ii = (float)((Sq - 2.0 * t * Sl + BK * t * t) / BK);
            const float gg = red[0] / (float)jme::NPAIR;
            out[0] = ii + gg;
            out[1] = ii;
            out[2] = gg;
        }
        // reset accumulators for next graph replay
        if (tid < jme::NPAIR) {
            atomicExch(&g_pairD[tid], 0ULL);
            atomicExch(&g_pairC[tid], 0u);
        }
        if (tid == 0) {
            atomicExch(&g_sq, 0ULL);
            atomicExch(&g_sl, 0ULL);
            atomicExch(&g_ts, 0ULL);
            atomicExch(&g_done, 0u);
        }
    }
}

// ------------------------------- launch ------------------------------------
extern "C" void kernel_launch(void* const* d_in, const int* in_sizes, int n_in,
                              void* d_out, int out_size) {
    const float* pred  = (const float*)d_in[0];
    const float* truth = (const float*)d_in[1];
    const int*   ug    = (const int*)  d_in[2];
    const int*   ig    = (const int*)  d_in[3];
    float* out = (float*)d_out;

    k_row<<<jme::B, 256>>>(pred, truth, ig, ug, out);
}

// round 8
// speedup vs baseline: 1.8898x; 1.8898x over previous
#include <cuda_runtime.h>
#include <stdint.h>

// ============================================================================
// JMEFairnessLoss — SINGLE kernel:
//   phase A: truth row-sum + threshold top-100 (exact radix fallback)
//   phase B: gumbel soft-rank exposure, dense tanh loop (round-6 form:
//            antisymmetric smem staging REVERTED — it was L1/alu-bound)
//   epilogue: fixed-point integer atomics (deterministic) + last-block
//             ticket finalize -> (total, ii, gg); accumulators self-reset.
// ============================================================================

namespace jme {
constexpr int B      = 1024;
constexpr int NITEMS = 10000;
constexpr int TOPK   = 100;
constexpr int NS     = 10;
constexpr int NIG    = 16;
constexpr int NPAIR  = 128;
constexpr int NTASK  = NS * TOPK;     // 1000
constexpr int CAND   = 256;
}

// ---- global accumulators (all raw sums are >= 0; fixed-point, exact) ------
__device__ unsigned long long g_pairD[jme::NPAIR];   // sum e  * 2^32 per (ug,ig)
__device__ unsigned int       g_pairC[jme::NPAIR];   // counts (exact ints)
__device__ unsigned long long g_sq;                  // sum e^2 * 2^32
__device__ unsigned long long g_sl;                  // sum e   * 2^32
__device__ unsigned long long g_ts;                  // sum truth * 2^26
__device__ unsigned int       g_done;

// ------------------------------- threefry2x32 (JAX-exact, key=(0,1)) -------
__device__ __forceinline__ void tf_round(uint32_t& x0, uint32_t& x1, int r) {
    x0 += x1;
    x1 = __funnelshift_l(x1, x1, r);
    x1 ^= x0;
}
__device__ __forceinline__ uint2 threefry01(uint32_t x0, uint32_t x1) {
    const uint32_t k0 = 0u, k1 = 1u, k2 = 0x1BD11BDBu;
    x0 += k0; x1 += k1;
    tf_round(x0,x1,13); tf_round(x0,x1,15); tf_round(x0,x1,26); tf_round(x0,x1,6);
    x0 += k1; x1 += k2 + 1u;
    tf_round(x0,x1,17); tf_round(x0,x1,29); tf_round(x0,x1,16); tf_round(x0,x1,24);
    x0 += k2; x1 += k0 + 2u;
    tf_round(x0,x1,13); tf_round(x0,x1,15); tf_round(x0,x1,26); tf_round(x0,x1,6);
    x0 += k0; x1 += k1 + 3u;
    tf_round(x0,x1,17); tf_round(x0,x1,29); tf_round(x0,x1,16); tf_round(x0,x1,24);
    x0 += k1; x1 += k2 + 4u;
    tf_round(x0,x1,13); tf_round(x0,x1,15); tf_round(x0,x1,26); tf_round(x0,x1,6);
    x0 += k2; x1 += k0 + 5u;
    return make_uint2(x0, x1);
}
__device__ __forceinline__ float gumbel_at(int lin) {
    uint2 r = threefry01(0u, (uint32_t)lin);
    uint32_t bits = r.x ^ r.y;
    float f = __uint_as_float((bits >> 9) | 0x3F800000u) - 1.0f;
    float u = fmaxf(1.17549435e-38f, f);
    return -__logf(-__logf(u));
}

// ------------------------------- key helpers -------------------------------
__device__ __forceinline__ uint32_t f2key(float f) {
    uint32_t u = __float_as_uint(f);
    return (u & 0x80000000u) ? ~u : (u | 0x80000000u);
}
__device__ __forceinline__ float key2f(uint32_t k) {
    uint32_t fb = (k & 0x80000000u) ? (k ^ 0x80000000u) : ~k;
    return __uint_as_float(fb);
}

// ------------------------------- the kernel --------------------------------
__global__ __launch_bounds__(256) void k_row(const float* __restrict__ pred,
                                             const float* __restrict__ truth,
                                             const int*   __restrict__ item_groups,
                                             const int*   __restrict__ user_groups,
                                             float* __restrict__ out) {
    __shared__ unsigned long long cand[jme::CAND];   // 2 KB
    __shared__ float sval[jme::TOPK];
    __shared__ int   s_ig[jme::TOPK];
    __shared__ float nz[jme::NS][jme::TOPK];         // noisy * 5
    __shared__ float expo_sb[jme::NTASK];            // aliased: red / hist
    __shared__ float sdelta[jme::TOPK];              // raw e per item
    __shared__ int s_cnt;
    __shared__ uint32_t s_prefix;
    __shared__ int s_rem;
    __shared__ int s_ticket;
    float*    red  = expo_sb;                        // reduction alias
    uint32_t* hist = (uint32_t*)expo_sb;             // fallback alias

    const int row = blockIdx.x, tid = threadIdx.x;
    const float4* rp4 = (const float4*)(pred  + (size_t)row * jme::NITEMS);
    const float4* tr4 = (const float4*)(truth + (size_t)row * jme::NITEMS);
    constexpr int N4 = jme::NITEMS / 4;              // 2500

    // =============== phase A: truth sum + top-100 gather ===================
    cand[tid] = 0ULL;
    if (tid == 0) s_cnt = 0;
    __syncthreads();

    const float THR = 2.10f;   // N(0,1): E[count>THR]=178, sd=13 (cap 256)
    float tsum = 0.0f;
    #pragma unroll 5
    for (int c = tid; c < N4; c += 256) {
        float4 v  = rp4[c];
        float4 tv = tr4[c];
        tsum += (tv.x + tv.y) + (tv.z + tv.w);
        const float vv[4] = {v.x, v.y, v.z, v.w};
        #pragma unroll
        for (int e = 0; e < 4; ++e) {
            if (vv[e] > THR) {
                int pos = atomicAdd(&s_cnt, 1);
                if (pos < jme::CAND)
                    cand[pos] = (((unsigned long long)f2key(vv[e])) << 32)
                              | (uint32_t)(0xFFFFFFFFu - (uint32_t)(4 * c + e));
            }
        }
    }
    red[tid] = tsum;
    __syncthreads();
    for (int o = 128; o > 0; o >>= 1) {
        if (tid < o) red[tid] += red[tid + o];
        __syncthreads();
    }
    if (tid == 0)
        atomicAdd(&g_ts, (unsigned long long)__double2ll_rn((double)red[0] * 67108864.0));
    __syncthreads();

    // exact fallback (statistically never taken; correctness for any input)
    if (s_cnt < jme::TOPK || s_cnt > jme::CAND) {
        const float* rp = pred + (size_t)row * jme::NITEMS;
        if (tid == 0) { s_rem = jme::TOPK; s_prefix = 0u; }
        __syncthreads();
        uint32_t prefix = 0u;
        for (int shift = 24; shift >= 0; shift -= 8) {
            hist[tid] = 0u;
            __syncthreads();
            const uint32_t himask = (shift == 24) ? 0u : (0xFFFFFFFFu << (shift + 8));
            for (int i = tid; i < jme::NITEMS; i += 256) {
                uint32_t k = f2key(rp[i]);
                if ((k & himask) == prefix)
                    atomicAdd(&hist[(k >> shift) & 0xFF], 1u);
            }
            __syncthreads();
            if (tid == 0) {
                int cum = 0, sel = 0;
                for (int b = 255; b >= 0; --b) {
                    int h = (int)hist[b];
                    if (cum + h >= s_rem) { sel = b; s_rem -= cum; break; }
                    cum += h;
                }
                s_prefix = prefix | ((uint32_t)sel << shift);
            }
            __syncthreads();
            prefix = s_prefix;
            __syncthreads();
        }
        const uint32_t T = prefix;   // exact 100th-largest key
        cand[tid] = 0ULL;
        if (tid == 0) s_cnt = 0;
        __syncthreads();
        for (int i = tid; i < jme::NITEMS; i += 256) {
            uint32_t k = f2key(rp[i]);
            if (k >= T) {
                int pos = atomicAdd(&s_cnt, 1);
                if (pos < jme::CAND)
                    cand[pos] = (((unsigned long long)k) << 32)
                              | (uint32_t)(0xFFFFFFFFu - (uint32_t)i);
            }
        }
        __syncthreads();
    }

    // rank-by-count: rank = #{j : cand[j] > cand[i]}; scatter top-100
    {
        unsigned long long e = cand[tid];
        int r = 0;
        #pragma unroll 8
        for (int j = 0; j < jme::CAND; ++j) r += (cand[j] > e);
        if (e != 0ULL && r < jme::TOPK) {
            sval[r] = key2f((uint32_t)(e >> 32));
            s_ig[r] = item_groups[0xFFFFFFFFu - (uint32_t)e];
        }
    }
    __syncthreads();

    // =============== phase B: exposure (dense tanh, round-6 form) ==========
    for (int tk = tid; tk < jme::NTASK; tk += 256) {
        int s = tk / jme::TOPK, i = tk - s * jme::TOPK;
        int lin = (s * jme::B + row) * jme::TOPK + i;
        nz[s][i] = (sval[i] + gumbel_at(lin)) * 5.0f;
    }
    __syncthreads();

    const float L2G = -0.3219280948873623f;     // log2(0.8)
    for (int tk = tid; tk < jme::NTASK; tk += 256) {
        int s = tk / jme::TOPK, i = tk - s * jme::TOPK;
        const float* rowp = nz[s];
        const float vi = rowp[i];
        float t0 = 0.0f, t1 = 0.0f, t2 = 0.0f, t3 = 0.0f;
        #pragma unroll 5
        for (int j = 0; j < jme::TOPK; j += 4) {
            float a0, a1, a2, a3;
            asm("tanh.approx.f32 %0, %1;" : "=f"(a0) : "f"(vi - rowp[j]));
            asm("tanh.approx.f32 %0, %1;" : "=f"(a1) : "f"(vi - rowp[j + 1]));
            asm("tanh.approx.f32 %0, %1;" : "=f"(a2) : "f"(vi - rowp[j + 2]));
            asm("tanh.approx.f32 %0, %1;" : "=f"(a3) : "f"(vi - rowp[j + 3]));
            t0 += a0; t1 += a1; t2 += a2; t3 += a3;
        }
        float T = (t0 + t1) + (t2 + t3);
        float ex;
        asm("ex2.approx.f32 %0, %1;" : "=f"(ex) : "f"(fmaf(T, 0.5f * L2G, 49.5f * L2G)));
        expo_sb[tk] = ex;
    }
    __syncthreads();

    if (tid < jme::TOPK) {
        float acc = 0.0f;
        #pragma unroll
        for (int s = 0; s < jme::NS; ++s) acc += expo_sb[s * jme::TOPK + tid];
        sdelta[tid] = acc * 0.1f;           // raw e_i (t deferred)
    }
    __syncthreads();

    // =============== per-row partials -> global integer atomics ============
    if (tid == 0) {
        float sq = 0.0f, sl = 0.0f;
        for (int i = 0; i < jme::TOPK; ++i) {
            float e = sdelta[i];
            sq += e * e; sl += e;
        }
        atomicAdd(&g_sq, (unsigned long long)__double2ll_rn((double)sq * 4294967296.0));
        atomicAdd(&g_sl, (unsigned long long)__double2ll_rn((double)sl * 4294967296.0));
    }
    if (tid < jme::NIG) {
        float sD = 0.0f, c = 0.0f;
        for (int i = 0; i < jme::TOPK; ++i)
            if (s_ig[i] == tid) { sD += sdelta[i]; c += 1.0f; }
        const int ug = user_groups[row];
        atomicAdd(&g_pairD[ug * jme::NIG + tid],
                  (unsigned long long)__double2ll_rn((double)sD * 4294967296.0));
        atomicAdd(&g_pairC[ug * jme::NIG + tid], (unsigned int)c);
    }

    // =============== last-block ticket: finalize ============================
    __threadfence();
    if (tid == 0) s_ticket = (int)atomicAdd(&g_done, 1u);
    __syncthreads();
    if (s_ticket == jme::B - 1) {
        const double t = (double)(long long)__ldcg((const long long*)&g_ts)
                         / 67108864.0 / (double)(jme::B * jme::NITEMS);
        float a2 = 0.0f;
        if (tid < jme::NPAIR) {
            double D = (double)(long long)__ldcg((const long long*)&g_pairD[tid])
                       / 4294967296.0;
            double C = (double)__ldcg((const unsigned int*)&g_pairC[tid]);
            double avg = (C > 0.0) ? ((D - t * C) / fmax(C, 1.0)) : 0.0;
            a2 = (float)(avg * avg);
        }
        red[tid] = a2;
        __syncthreads();
        for (int o = 128; o > 0; o >>= 1) {
            if (tid < o) red[tid] += red[tid + o];
            __syncthreads();
        }
        if (tid == 0) {
            const double BK = (double)(jme::B * jme::TOPK);
            double Sq = (double)(long long)__ldcg((const long long*)&g_sq) / 4294967296.0;
            double Sl = (double)(long long)__ldcg((const long long*)&g_sl) / 4294967296.0;
            const float ii = (float)((Sq - 2.0 * t * Sl + BK * t * t) / BK);
            const float gg = red[0] / (float)jme::NPAIR;
            out[0] = ii + gg;
            out[1] = ii;
            out[2] = gg;
        }
        // reset accumulators for next graph replay
        if (tid < jme::NPAIR) {
            atomicExch(&g_pairD[tid], 0ULL);
            atomicExch(&g_pairC[tid], 0u);
        }
        if (tid == 0) {
            atomicExch(&g_sq, 0ULL);
            atomicExch(&g_sl, 0ULL);
            atomicExch(&g_ts, 0ULL);
            atomicExch(&g_done, 0u);
        }
    }
}

// ------------------------------- launch ------------------------------------
extern "C" void kernel_launch(void* const* d_in, const int* in_sizes, int n_in,
                              void* d_out, int out_size) {
    const float* pred  = (const float*)d_in[0];
    const float* truth = (const float*)d_in[1];
    const int*   ug    = (const int*)  d_in[2];
    const int*   ig    = (const int*)  d_in[3];
    float* out = (float*)d_out;

    k_row<<<jme::B, 256>>>(pred, truth, ig, ug, out);
}

// round 9
// speedup vs baseline: 1.8923x; 1.0013x over previous
#include <cuda_runtime.h>
#include <stdint.h>

// ============================================================================
// JMEFairnessLoss — SINGLE kernel:
//   phase A: threshold top-100 gather on pred (exact radix fallback)
//   phase B: gumbel soft-rank exposure (dense tanh) WITH truth-row loads
//            interleaved under the MUFU shadow (truth sum is independent)
//   epilogue: fixed-point integer atomics (deterministic) + last-block
//             ticket finalize -> (total, ii, gg); accumulators self-reset.
// ============================================================================

namespace jme {
constexpr int B      = 1024;
constexpr int NITEMS = 10000;
constexpr int TOPK   = 100;
constexpr int NS     = 10;
constexpr int NIG    = 16;
constexpr int NPAIR  = 128;
constexpr int NTASK  = NS * TOPK;     // 1000
constexpr int CAND   = 256;
}

// ---- global accumulators (all raw sums are >= 0; fixed-point, exact) ------
__device__ unsigned long long g_pairD[jme::NPAIR];   // sum e  * 2^32 per (ug,ig)
__device__ unsigned int       g_pairC[jme::NPAIR];   // counts (exact ints)
__device__ unsigned long long g_sq;                  // sum e^2 * 2^32
__device__ unsigned long long g_sl;                  // sum e   * 2^32
__device__ unsigned long long g_ts;                  // sum truth * 2^26
__device__ unsigned int       g_done;

// ------------------------------- threefry2x32 (JAX-exact, key=(0,1)) -------
__device__ __forceinline__ void tf_round(uint32_t& x0, uint32_t& x1, int r) {
    x0 += x1;
    x1 = __funnelshift_l(x1, x1, r);
    x1 ^= x0;
}
__device__ __forceinline__ uint2 threefry01(uint32_t x0, uint32_t x1) {
    const uint32_t k0 = 0u, k1 = 1u, k2 = 0x1BD11BDBu;
    x0 += k0; x1 += k1;
    tf_round(x0,x1,13); tf_round(x0,x1,15); tf_round(x0,x1,26); tf_round(x0,x1,6);
    x0 += k1; x1 += k2 + 1u;
    tf_round(x0,x1,17); tf_round(x0,x1,29); tf_round(x0,x1,16); tf_round(x0,x1,24);
    x0 += k2; x1 += k0 + 2u;
    tf_round(x0,x1,13); tf_round(x0,x1,15); tf_round(x0,x1,26); tf_round(x0,x1,6);
    x0 += k0; x1 += k1 + 3u;
    tf_round(x0,x1,17); tf_round(x0,x1,29); tf_round(x0,x1,16); tf_round(x0,x1,24);
    x0 += k1; x1 += k2 + 4u;
    tf_round(x0,x1,13); tf_round(x0,x1,15); tf_round(x0,x1,26); tf_round(x0,x1,6);
    x0 += k2; x1 += k0 + 5u;
    return make_uint2(x0, x1);
}
__device__ __forceinline__ float gumbel_at(int lin) {
    uint2 r = threefry01(0u, (uint32_t)lin);
    uint32_t bits = r.x ^ r.y;
    float f = __uint_as_float((bits >> 9) | 0x3F800000u) - 1.0f;
    float u = fmaxf(1.17549435e-38f, f);
    return -__logf(-__logf(u));
}

// ------------------------------- key helpers -------------------------------
__device__ __forceinline__ uint32_t f2key(float f) {
    uint32_t u = __float_as_uint(f);
    return (u & 0x80000000u) ? ~u : (u | 0x80000000u);
}
__device__ __forceinline__ float key2f(uint32_t k) {
    uint32_t fb = (k & 0x80000000u) ? (k ^ 0x80000000u) : ~k;
    return __uint_as_float(fb);
}

// ------------------------------- the kernel --------------------------------
__global__ __launch_bounds__(256) void k_row(const float* __restrict__ pred,
                                             const float* __restrict__ truth,
                                             const int*   __restrict__ item_groups,
                                             const int*   __restrict__ user_groups,
                                             float* __restrict__ out) {
    __shared__ unsigned long long cand[jme::CAND];   // 2 KB
    __shared__ float sval[jme::TOPK];
    __shared__ int   s_ig[jme::TOPK];
    __shared__ float nz[jme::NS][jme::TOPK];         // noisy * 5
    __shared__ float expo_sb[jme::NTASK];            // aliased: red / hist
    __shared__ float sdelta[jme::TOPK];              // raw e per item
    __shared__ int s_cnt;
    __shared__ uint32_t s_prefix;
    __shared__ int s_rem;
    __shared__ int s_ticket;
    float*    red  = expo_sb;                        // reduction alias
    uint32_t* hist = (uint32_t*)expo_sb;             // fallback alias

    const int row = blockIdx.x, tid = threadIdx.x;
    const float4* rp4 = (const float4*)(pred  + (size_t)row * jme::NITEMS);
    const float4* tr4 = (const float4*)(truth + (size_t)row * jme::NITEMS);
    constexpr int N4 = jme::NITEMS / 4;              // 2500

    // =============== phase A: top-100 gather (pred only) ===================
    cand[tid] = 0ULL;
    if (tid == 0) s_cnt = 0;
    __syncthreads();

    const float THR = 2.10f;   // N(0,1): E[count>THR]=178, sd=13 (cap 256)
    #pragma unroll 5
    for (int c = tid; c < N4; c += 256) {
        float4 v = rp4[c];
        const float vv[4] = {v.x, v.y, v.z, v.w};
        #pragma unroll
        for (int e = 0; e < 4; ++e) {
            if (vv[e] > THR) {
                int pos = atomicAdd(&s_cnt, 1);
                if (pos < jme::CAND)
                    cand[pos] = (((unsigned long long)f2key(vv[e])) << 32)
                              | (uint32_t)(0xFFFFFFFFu - (uint32_t)(4 * c + e));
            }
        }
    }
    __syncthreads();

    // exact fallback (statistically never taken; correctness for any input)
    if (s_cnt < jme::TOPK || s_cnt > jme::CAND) {
        const float* rp = pred + (size_t)row * jme::NITEMS;
        if (tid == 0) { s_rem = jme::TOPK; s_prefix = 0u; }
        __syncthreads();
        uint32_t prefix = 0u;
        for (int shift = 24; shift >= 0; shift -= 8) {
            hist[tid] = 0u;
            __syncthreads();
            const uint32_t himask = (shift == 24) ? 0u : (0xFFFFFFFFu << (shift + 8));
            for (int i = tid; i < jme::NITEMS; i += 256) {
                uint32_t k = f2key(rp[i]);
                if ((k & himask) == prefix)
                    atomicAdd(&hist[(k >> shift) & 0xFF], 1u);
            }
            __syncthreads();
            if (tid == 0) {
                int cum = 0, sel = 0;
                for (int b = 255; b >= 0; --b) {
                    int h = (int)hist[b];
                    if (cum + h >= s_rem) { sel = b; s_rem -= cum; break; }
                    cum += h;
                }
                s_prefix = prefix | ((uint32_t)sel << shift);
            }
            __syncthreads();
            prefix = s_prefix;
            __syncthreads();
        }
        const uint32_t T = prefix;   // exact 100th-largest key
        cand[tid] = 0ULL;
        if (tid == 0) s_cnt = 0;
        __syncthreads();
        for (int i = tid; i < jme::NITEMS; i += 256) {
            uint32_t k = f2key(rp[i]);
            if (k >= T) {
                int pos = atomicAdd(&s_cnt, 1);
                if (pos < jme::CAND)
                    cand[pos] = (((unsigned long long)k) << 32)
                              | (uint32_t)(0xFFFFFFFFu - (uint32_t)i);
            }
        }
        __syncthreads();
    }

    // rank-by-count: rank = #{j : cand[j] > cand[i]}; scatter top-100
    {
        unsigned long long e = cand[tid];
        int r = 0;
        #pragma unroll 8
        for (int j = 0; j < jme::CAND; ++j) r += (cand[j] > e);
        if (e != 0ULL && r < jme::TOPK) {
            sval[r] = key2f((uint32_t)(e >> 32));
            s_ig[r] = item_groups[0xFFFFFFFFu - (uint32_t)e];
        }
    }
    __syncthreads();

    // =============== phase B: exposure + hidden truth loads ================
    for (int tk = tid; tk < jme::NTASK; tk += 256) {
        int s = tk / jme::TOPK, i = tk - s * jme::TOPK;
        int lin = (s * jme::B + row) * jme::TOPK + i;
        nz[s][i] = (sval[i] + gumbel_at(lin)) * 5.0f;
    }
    __syncthreads();

    const float L2G = -0.3219280948873623f;     // log2(0.8)
    float tacc = 0.0f;                          // truth partial (hidden loads)
    #pragma unroll
    for (int m = 0; m < 4; ++m) {
        const int tk = tid + 256 * m;

        // ---- issue truth loads for this slice (consumed after tanh loop) --
        // chunks q = m, m+4, and (m<2) m+8 cover q = 0..9 exactly once.
        float4 p0 = tr4[tid + 256 * m];                      // c <= 1023
        float4 p1 = tr4[tid + 256 * (m + 4)];                // c <= 2047
        float4 p2 = make_float4(0.f, 0.f, 0.f, 0.f);
        if (m < 2) {
            int c2 = tid + 256 * (m + 8);
            if (c2 < N4) p2 = tr4[c2];                       // guard 2500
        }

        // ---- dense tanh task -----------------------------------------------
        if (tk < jme::NTASK) {
            const int s = tk / jme::TOPK, i = tk - s * jme::TOPK;
            const float* rowp = nz[s];
            const float vi = rowp[i];
            float t0 = 0.0f, t1 = 0.0f, t2 = 0.0f, t3 = 0.0f;
            #pragma unroll 5
            for (int j = 0; j < jme::TOPK; j += 4) {
                float a0, a1, a2, a3;
                asm("tanh.approx.f32 %0, %1;" : "=f"(a0) : "f"(vi - rowp[j]));
                asm("tanh.approx.f32 %0, %1;" : "=f"(a1) : "f"(vi - rowp[j + 1]));
                asm("tanh.approx.f32 %0, %1;" : "=f"(a2) : "f"(vi - rowp[j + 2]));
                asm("tanh.approx.f32 %0, %1;" : "=f"(a3) : "f"(vi - rowp[j + 3]));
                t0 += a0; t1 += a1; t2 += a2; t3 += a3;
            }
            float T = (t0 + t1) + (t2 + t3);
            float ex;
            asm("ex2.approx.f32 %0, %1;" : "=f"(ex)
                : "f"(fmaf(T, 0.5f * L2G, 49.5f * L2G)));
            expo_sb[tk] = ex;
        }

        // ---- consume truth loads (latency long gone) -----------------------
        tacc += ((p0.x + p0.y) + (p0.z + p0.w))
              + ((p1.x + p1.y) + (p1.z + p1.w))
              + ((p2.x + p2.y) + (p2.z + p2.w));
    }
    __syncthreads();

    if (tid < jme::TOPK) {
        float acc = 0.0f;
        #pragma unroll
        for (int s = 0; s < jme::NS; ++s) acc += expo_sb[s * jme::TOPK + tid];
        sdelta[tid] = acc * 0.1f;           // raw e_i (t deferred)
    }
    __syncthreads();

    // truth reduction (expo_sb now reusable as red)
    red[tid] = tacc;
    __syncthreads();
    for (int o = 128; o > 0; o >>= 1) {
        if (tid < o) red[tid] += red[tid + o];
        __syncthreads();
    }
    if (tid == 0)
        atomicAdd(&g_ts, (unsigned long long)__double2ll_rn((double)red[0] * 67108864.0));

    // =============== per-row partials -> global integer atomics ============
    if (tid == 1) {
        float sq = 0.0f, sl = 0.0f;
        for (int i = 0; i < jme::TOPK; ++i) {
            float e = sdelta[i];
            sq += e * e; sl += e;
        }
        atomicAdd(&g_sq, (unsigned long long)__double2ll_rn((double)sq * 4294967296.0));
        atomicAdd(&g_sl, (unsigned long long)__double2ll_rn((double)sl * 4294967296.0));
    }
    if (tid >= 32 && tid < 32 + jme::NIG) {
        const int g = tid - 32;
        float sD = 0.0f, c = 0.0f;
        for (int i = 0; i < jme::TOPK; ++i)
            if (s_ig[i] == g) { sD += sdelta[i]; c += 1.0f; }
        const int ug = user_groups[row];
        atomicAdd(&g_pairD[ug * jme::NIG + g],
                  (unsigned long long)__double2ll_rn((double)sD * 4294967296.0));
        atomicAdd(&g_pairC[ug * jme::NIG + g], (unsigned int)c);
    }

    // =============== last-block ticket: finalize ============================
    __threadfence();
    __syncthreads();
    if (tid == 0) s_ticket = (int)atomicAdd(&g_done, 1u);
    __syncthreads();
    if (s_ticket == jme::B - 1) {
        const double t = (double)(long long)__ldcg((const long long*)&g_ts)
                         / 67108864.0 / (double)(jme::B * jme::NITEMS);
        float a2 = 0.0f;
        if (tid < jme::NPAIR) {
            double D = (double)(long long)__ldcg((const long long*)&g_pairD[tid])
                       / 4294967296.0;
            double C = (double)__ldcg((const unsigned int*)&g_pairC[tid]);
            double avg = (C > 0.0) ? ((D - t * C) / fmax(C, 1.0)) : 0.0;
            a2 = (float)(avg * avg);
        }
        red[tid] = a2;
        __syncthreads();
        for (int o = 128; o > 0; o >>= 1) {
            if (tid < o) red[tid] += red[tid + o];
            __syncthreads();
        }
        if (tid == 0) {
            const double BK = (double)(jme::B * jme::TOPK);
            double Sq = (double)(long long)__ldcg((const long long*)&g_sq) / 4294967296.0;
            double Sl = (double)(long long)__ldcg((const long long*)&g_sl) / 4294967296.0;
            const float ii = (float)((Sq - 2.0 * t * Sl + BK * t * t) / BK);
            const float gg = red[0] / (float)jme::NPAIR;
            out[0] = ii + gg;
            out[1] = ii;
            out[2] = gg;
        }
        // reset accumulators for next graph replay
        if (tid < jme::NPAIR) {
            atomicExch(&g_pairD[tid], 0ULL);
            atomicExch(&g_pairC[tid], 0u);
        }
        if (tid == 0) {
            atomicExch(&g_sq, 0ULL);
            atomicExch(&g_sl, 0ULL);
            atomicExch(&g_ts, 0ULL);
            atomicExch(&g_done, 0u);
        }
    }
}

// ------------------------------- launch ------------------------------------
extern "C" void kernel_launch(void* const* d_in, const int* in_sizes, int n_in,
                              void* d_out, int out_size) {
    const float* pred  = (const float*)d_in[0];
    const float* truth = (const float*)d_in[1];
    const int*   ug    = (const int*)  d_in[2];
    const int*   ig    = (const int*)  d_in[3];
    float* out = (float*)d_out;

    k_row<<<jme::B, 256>>>(pred, truth, ig, ug, out);
}